// round 13
// baseline (speedup 1.0000x reference)
#include <cuda_runtime.h>
#include <cuda_bf16.h>
#include <stdint.h>

// x: (B=8, C=3, H=1024, W=1024) fp32; patch=24, stride=16, reflect m=4
// out: (8*64*64, 576, 3) fp32 = 56,623,104 elems (+ maybe (nH,nW)=(64,64)).
#define PATCH_ELEMS 56623104u
#define NROWCTAS 6144u         // 4 image-pairs x 64 ph x 24 iu
#define THREADS  384u          // one thread per (pw, jq) quad of the row
#define B_OFF_IN  (12u << 20)  // +4 images in input floats
#define B_OFF_OUT 7077888u     // +4 images in output float4s (4*4096*432)

__device__ __forceinline__ int reflect1024(int v) {
    v = (v < 0) ? -v : v;                 // jnp 'reflect' (no edge repeat)
    v = (v >= 1024) ? (2046 - v) : v;
    return v;
}

__device__ __forceinline__ unsigned smem_u32(const void* p) {
    return (unsigned)__cvta_generic_to_shared(p);
}

__global__ __launch_bounds__(THREADS, 5)
void Patcher_78280073937146_kernel(const float* __restrict__ x,
                                   float* __restrict__ out,
                                   unsigned out_elems) {
    // raw channel-plane staging: [img*3+ch][quad t] float4, plane-major (36.9 KB)
    __shared__ float4 raw[6u * THREADS];
    float* rawf = reinterpret_cast<float*>(raw);

    unsigned bid = blockIdx.x;
    unsigned t   = threadIdx.x;

    if (bid >= NROWCTAS) {
        // trailing (nH, nW) = (64, 64) slots, if the harness appends them
        unsigned e = PATCH_ELEMS + (bid - NROWCTAS) * THREADS + t;
        if (e < out_elems) out[e] = 64.0f;
        return;
    }

    unsigned lane = t & 31u;
    unsigned w    = t >> 5;

    // ---- CTA decode: one (b4, ph, iu) row for images b4 and b4+4 ----
    unsigned b4  = bid / 1536u;           // 0..3
    unsigned rem = bid - b4 * 1536u;
    unsigned ph  = rem / 24u;             // 0..63
    unsigned iu  = rem - ph * 24u;        // 0..23

    int y = reflect1024((int)(ph * 16u + iu) - 4);
    unsigned baseA = ((b4 * 3u) << 20) + (((unsigned)y) << 10);

    // ---- per-thread: quad (pw, jq); 6 register-free cp.async loads ----
    unsigned pw = t / 6u;
    unsigned jq = t - pw * 6u;
    int x0 = (int)(pw * 16u + (jq << 2)) - 4;   // -4 .. 1024, 16B-aligned

    if ((unsigned)x0 <= 1020u) {
        #pragma unroll
        for (unsigned p = 0; p < 6u; ++p) {
            unsigned gbase = (p < 3u) ? (baseA + (p << 20))
                                      : (baseA + B_OFF_IN + ((p - 3u) << 20));
            unsigned dst = smem_u32(&raw[p * THREADS + t]);
            const float* src = x + gbase + (unsigned)x0;
            asm volatile("cp.async.cg.shared.global [%0], [%1], 16;"
                         :: "r"(dst), "l"(src) : "memory");
        }
        asm volatile("cp.async.commit_group;" ::: "memory");
    } else {
        // threads 0 (x0=-4) and 383 (x0=1024) only: reflected scalar gather
        #pragma unroll
        for (unsigned p = 0; p < 6u; ++p) {
            unsigned gbase = (p < 3u) ? (baseA + (p << 20))
                                      : (baseA + B_OFF_IN + ((p - 3u) << 20));
            float tv[4];
            #pragma unroll
            for (int k = 0; k < 4; ++k)
                tv[k] = x[gbase + (unsigned)reflect1024(x0 + k)];
            raw[p * THREADS + t] = make_float4(tv[0], tv[1], tv[2], tv[3]);
        }
    }
    asm volatile("cp.async.wait_group 0;" ::: "memory");
    __syncwarp();   // exchange is warp-local: emit f in [96w,96w+96) reads q in [32w,32w+32)

    // ---- emit: coalesced 512B STG bursts per warp, both images ----
    unsigned outBase = ((b4 << 12) + (ph << 6)) * 432u + iu * 18u;
    float4* ov = reinterpret_cast<float4*>(out);
    unsigned f0 = w * 96u + lane;

    #pragma unroll
    for (unsigned img = 0; img < 2u; ++img) {
        unsigned planeOff = img * 3u * (THREADS * 4u);  // floats
        unsigned outOff   = outBase + img * B_OFF_OUT;
        #pragma unroll
        for (unsigned i = 0; i < 3u; ++i) {
            unsigned f = f0 + i * 32u;    // 0..1151
            unsigned q = f / 3u;
            unsigned k = f - q * 3u;      // slot within quad
            float v[4];
            #pragma unroll
            for (unsigned j = 0; j < 4u; ++j) {
                unsigned e  = 4u * k + j; // 0..11: interleaved elem within quad
                unsigned ch = e % 3u;
                unsigned px = e / 3u;
                v[j] = rawf[planeOff + ch * (THREADS * 4u) + (q << 2) + px];
            }
            unsigned pwS = f / 18u;
            unsigned r   = f - pwS * 18u;
            __stcs(ov + outOff + pwS * 432u + r,
                   make_float4(v[0], v[1], v[2], v[3]));
        }
    }
}

extern "C" void kernel_launch(void* const* d_in, const int* in_sizes, int n_in,
                              void* d_out, int out_size) {
    const float* x = (const float*)d_in[0];
    float* out = (float*)d_out;
    unsigned out_elems = (unsigned)out_size;

    unsigned extraElems  = (out_elems > PATCH_ELEMS) ? (out_elems - PATCH_ELEMS) : 0u;
    unsigned extraBlocks = (extraElems + THREADS - 1u) / THREADS;
    Patcher_78280073937146_kernel<<<NROWCTAS + extraBlocks, THREADS>>>(x, out, out_elems);
}

// round 14
// speedup vs baseline: 1.2576x; 1.2576x over previous
#include <cuda_runtime.h>
#include <cuda_bf16.h>
#include <stdint.h>

// x: (B=8, C=3, H=1024, W=1024) fp32; patch=24, stride=16, reflect m=4
// out: (8*64*64, 576, 3) fp32 = 56,623,104 elems (+ maybe (nH,nW)=(64,64)).
#define PATCH_ELEMS 56623104u
#define NROWCTAS 6144u         // 4 image-pairs x 64 ph x 24 iu
#define THREADS  192u          // each thread: quads t and t+192 of the 384-quad row
#define B_OFF_IN  (12u << 20)  // +4 images in input floats
#define B_OFF_OUT 7077888u     // +4 images in output float4s (4*4096*432)

__device__ __forceinline__ int reflect1024(int v) {
    v = (v < 0) ? -v : v;                 // jnp 'reflect' (no edge repeat)
    v = (v >= 1024) ? (2046 - v) : v;
    return v;
}

__device__ __forceinline__ void gatherEdge(const float* __restrict__ x,
                                           unsigned baseA, int x0,
                                           float4& a0, float4& a1, float4& a2,
                                           float4& c0, float4& c1, float4& c2) {
    float ta[3][4], tb[3][4];
    #pragma unroll
    for (int k = 0; k < 4; ++k) {
        unsigned xr = (unsigned)reflect1024(x0 + k);
        #pragma unroll
        for (int c = 0; c < 3; ++c) {
            ta[c][k] = x[baseA + (((unsigned)c) << 20) + xr];
            tb[c][k] = x[baseA + B_OFF_IN + (((unsigned)c) << 20) + xr];
        }
    }
    a0 = make_float4(ta[0][0], ta[0][1], ta[0][2], ta[0][3]);
    a1 = make_float4(ta[1][0], ta[1][1], ta[1][2], ta[1][3]);
    a2 = make_float4(ta[2][0], ta[2][1], ta[2][2], ta[2][3]);
    c0 = make_float4(tb[0][0], tb[0][1], tb[0][2], tb[0][3]);
    c1 = make_float4(tb[1][0], tb[1][1], tb[1][2], tb[1][3]);
    c2 = make_float4(tb[2][0], tb[2][1], tb[2][2], tb[2][3]);
}

__global__ __launch_bounds__(THREADS, 5)
void Patcher_78280073937146_kernel(const float* __restrict__ x,
                                   float* __restrict__ out,
                                   unsigned out_elems) {
    __shared__ float4 smq[2][1152];       // 36.9 KB: images A and B, one row each

    unsigned bid = blockIdx.x;
    unsigned t   = threadIdx.x;

    if (bid >= NROWCTAS) {
        // trailing (nH, nW) = (64, 64) slots, if the harness appends them
        unsigned e = PATCH_ELEMS + (bid - NROWCTAS) * THREADS + t;
        if (e < out_elems) out[e] = 64.0f;
        return;
    }

    unsigned lane = t & 31u;
    unsigned w    = t >> 5;               // 0..5

    // ---- CTA decode: one (b4, ph, iu) row for images b4 and b4+4 ----
    unsigned b4  = bid / 1536u;           // 0..3
    unsigned rem = bid - b4 * 1536u;
    unsigned ph  = rem / 24u;             // 0..63
    unsigned iu  = rem - ph * 24u;        // 0..23

    int y = reflect1024((int)(ph * 16u + iu) - 4);
    unsigned baseA = ((b4 * 3u) << 20) + (((unsigned)y) << 10);
    unsigned baseB = baseA + B_OFF_IN;

    // ---- per-thread: quads q0=t (pw), q1=t+192 (pw+32); 12 batched LDG.128 ----
    unsigned pw = t / 6u;                 // 0..31
    unsigned jq = t - pw * 6u;            // 0..5
    int x0 = (int)(pw * 16u + (jq << 2)) - 4;   // -4 .. 512 (16B-aligned)
    int x1 = x0 + 512;                          // 508 .. 1024

    float4 A0q0, A1q0, A2q0, B0q0, B1q0, B2q0;  // quad0: img A/B, planes 0..2
    float4 A0q1, A1q1, A2q1, B0q1, B1q1, B2q1;  // quad1

    bool v0 = ((unsigned)x0 <= 1020u);    // false only for t==0  (x0 == -4)
    bool v1 = ((unsigned)x1 <= 1020u);    // false only for t==191 (x1 == 1024)

    if (v0 & v1) {
        // hot path: 12 independent front-batched LDG.128 (MLP = 12)
        const float* pa0 = x + baseA + (unsigned)x0;
        const float* pb0 = x + baseB + (unsigned)x0;
        const float* pa1 = x + baseA + (unsigned)x1;
        const float* pb1 = x + baseB + (unsigned)x1;
        A0q0 = *reinterpret_cast<const float4*>(pa0);
        A1q0 = *reinterpret_cast<const float4*>(pa0 + (1u << 20));
        A2q0 = *reinterpret_cast<const float4*>(pa0 + (2u << 20));
        B0q0 = *reinterpret_cast<const float4*>(pb0);
        B1q0 = *reinterpret_cast<const float4*>(pb0 + (1u << 20));
        B2q0 = *reinterpret_cast<const float4*>(pb0 + (2u << 20));
        A0q1 = *reinterpret_cast<const float4*>(pa1);
        A1q1 = *reinterpret_cast<const float4*>(pa1 + (1u << 20));
        A2q1 = *reinterpret_cast<const float4*>(pa1 + (2u << 20));
        B0q1 = *reinterpret_cast<const float4*>(pb1);
        B1q1 = *reinterpret_cast<const float4*>(pb1 + (1u << 20));
        B2q1 = *reinterpret_cast<const float4*>(pb1 + (2u << 20));
    } else {
        // rare: t==0 or t==191 — one quad reflected, the other vector
        if (v0) {
            const float* pa0 = x + baseA + (unsigned)x0;
            const float* pb0 = x + baseB + (unsigned)x0;
            A0q0 = *reinterpret_cast<const float4*>(pa0);
            A1q0 = *reinterpret_cast<const float4*>(pa0 + (1u << 20));
            A2q0 = *reinterpret_cast<const float4*>(pa0 + (2u << 20));
            B0q0 = *reinterpret_cast<const float4*>(pb0);
            B1q0 = *reinterpret_cast<const float4*>(pb0 + (1u << 20));
            B2q0 = *reinterpret_cast<const float4*>(pb0 + (2u << 20));
        } else {
            gatherEdge(x, baseA, x0, A0q0, A1q0, A2q0, B0q0, B1q0, B2q0);
        }
        if (v1) {
            const float* pa1 = x + baseA + (unsigned)x1;
            const float* pb1 = x + baseB + (unsigned)x1;
            A0q1 = *reinterpret_cast<const float4*>(pa1);
            A1q1 = *reinterpret_cast<const float4*>(pa1 + (1u << 20));
            A2q1 = *reinterpret_cast<const float4*>(pa1 + (2u << 20));
            B0q1 = *reinterpret_cast<const float4*>(pb1);
            B1q1 = *reinterpret_cast<const float4*>(pb1 + (1u << 20));
            B2q1 = *reinterpret_cast<const float4*>(pb1 + (2u << 20));
        } else {
            gatherEdge(x, baseA, x1, A0q1, A1q1, A2q1, B0q1, B1q1, B2q1);
        }
    }

    // ---- permute channel-major -> (pixel, channel); stage (warp-local) ----
    unsigned s0 = t * 3u;                 // quad0 slots
    unsigned s1 = (t + 192u) * 3u;        // quad1 slots
    smq[0][s0 + 0u] = make_float4(A0q0.x, A1q0.x, A2q0.x, A0q0.y);
    smq[0][s0 + 1u] = make_float4(A1q0.y, A2q0.y, A0q0.z, A1q0.z);
    smq[0][s0 + 2u] = make_float4(A2q0.z, A0q0.w, A1q0.w, A2q0.w);
    smq[0][s1 + 0u] = make_float4(A0q1.x, A1q1.x, A2q1.x, A0q1.y);
    smq[0][s1 + 1u] = make_float4(A1q1.y, A2q1.y, A0q1.z, A1q1.z);
    smq[0][s1 + 2u] = make_float4(A2q1.z, A0q1.w, A1q1.w, A2q1.w);
    smq[1][s0 + 0u] = make_float4(B0q0.x, B1q0.x, B2q0.x, B0q0.y);
    smq[1][s0 + 1u] = make_float4(B1q0.y, B2q0.y, B0q0.z, B1q0.z);
    smq[1][s0 + 2u] = make_float4(B2q0.z, B0q0.w, B1q0.w, B2q0.w);
    smq[1][s1 + 0u] = make_float4(B0q1.x, B1q1.x, B2q1.x, B0q1.y);
    smq[1][s1 + 1u] = make_float4(B1q1.y, B2q1.y, B0q1.z, B1q1.z);
    smq[1][s1 + 2u] = make_float4(B2q1.z, B0q1.w, B1q1.w, B2q1.w);
    __syncwarp();   // warp-local: warp w wrote quads 32w..32w+31 and 192+32w..

    // ---- emit: 12 coalesced 512B STG bursts (2 images x 2 halves x 3) ----
    unsigned outBase = ((b4 << 12) + (ph << 6)) * 432u + iu * 18u;
    float4* ov = reinterpret_cast<float4*>(out);
    unsigned f0 = w * 96u + lane;

    #pragma unroll
    for (unsigned img = 0; img < 2u; ++img) {
        unsigned outOff = outBase + img * B_OFF_OUT;
        #pragma unroll
        for (unsigned half = 0; half < 2u; ++half) {
            unsigned fh = f0 + half * 576u;
            #pragma unroll
            for (unsigned i = 0; i < 3u; ++i) {
                unsigned f   = fh + i * 32u;    // 0..1151
                unsigned pwS = f / 18u;
                unsigned r   = f - pwS * 18u;
                __stcs(ov + outOff + pwS * 432u + r, smq[img][f]);
            }
        }
    }
}

extern "C" void kernel_launch(void* const* d_in, const int* in_sizes, int n_in,
                              void* d_out, int out_size) {
    const float* x = (const float*)d_in[0];
    float* out = (float*)d_out;
    unsigned out_elems = (unsigned)out_size;

    unsigned extraElems  = (out_elems > PATCH_ELEMS) ? (out_elems - PATCH_ELEMS) : 0u;
    unsigned extraBlocks = (extraElems + THREADS - 1u) / THREADS;
    Patcher_78280073937146_kernel<<<NROWCTAS + extraBlocks, THREADS>>>(x, out, out_elems);
}

// round 15
// speedup vs baseline: 1.3102x; 1.0418x over previous
#include <cuda_runtime.h>
#include <cuda_bf16.h>
#include <stdint.h>

// x: (B=8, C=3, H=1024, W=1024) fp32; patch=24, stride=16, reflect m=4
// out: (8*64*64, 576, 3) fp32 = 56,623,104 elems (+ maybe (nH,nW)=(64,64)).
#define PATCH_ELEMS 56623104u
#define NROWCTAS 6144u         // 4 image-pairs x 64 ph x 24 iu
#define THREADS  384u          // one thread per (pw, jq) quad of the row
#define B_OFF_IN  (12u << 20)  // +4 images in input floats
#define B_OFF_OUT 7077888u     // +4 images in output float4s (4*4096*432)

__device__ __forceinline__ int reflect1024(int v) {
    v = (v < 0) ? -v : v;                 // jnp 'reflect' (no edge repeat)
    v = (v >= 1024) ? (2046 - v) : v;
    return v;
}

__global__ __launch_bounds__(THREADS, 4)
void Patcher_78280073937146_kernel(const float* __restrict__ x,
                                   float* __restrict__ out,
                                   unsigned out_elems) {
    // staged output rows, images A|B: [img][pw*18 + r] float4 (36.9 KB)
    __shared__ float4 smq[2][1152];

    unsigned bid = blockIdx.x;
    unsigned t   = threadIdx.x;

    if (bid >= NROWCTAS) {
        // trailing (nH, nW) = (64, 64) slots, if the harness appends them
        unsigned e = PATCH_ELEMS + (bid - NROWCTAS) * THREADS + t;
        if (e < out_elems) out[e] = 64.0f;
        return;
    }

    // ---- CTA decode: one (b4, ph, iu) row for images b4 and b4+4 ----
    unsigned b4  = bid / 1536u;           // 0..3
    unsigned rem = bid - b4 * 1536u;
    unsigned ph  = rem / 24u;             // 0..63
    unsigned iu  = rem - ph * 24u;        // 0..23

    int y = reflect1024((int)(ph * 16u + iu) - 4);
    unsigned baseA = ((b4 * 3u) << 20) + (((unsigned)y) << 10);
    unsigned baseB = baseA + B_OFF_IN;

    // ---- per-thread: quad (pw, jq), both images, 6 front-batched LDG.128 ----
    unsigned pw = t / 6u;
    unsigned jq = t - pw * 6u;
    int x0 = (int)(pw * 16u + (jq << 2)) - 4;   // -4 .. 1024, 16B-aligned

    float4 a0, a1, a2, c0, c1, c2;
    if ((unsigned)x0 <= 1020u) {
        const float* pa = x + baseA + (unsigned)x0;
        const float* pb = x + baseB + (unsigned)x0;
        a0 = *reinterpret_cast<const float4*>(pa);
        a1 = *reinterpret_cast<const float4*>(pa + (1u << 20));
        a2 = *reinterpret_cast<const float4*>(pa + (2u << 20));
        c0 = *reinterpret_cast<const float4*>(pb);
        c1 = *reinterpret_cast<const float4*>(pb + (1u << 20));
        c2 = *reinterpret_cast<const float4*>(pb + (2u << 20));
    } else {
        // threads 0 (x0=-4) and 383 (x0=1024) only: reflected scalar gather
        float ta[3][4], tb[3][4];
        #pragma unroll
        for (int k = 0; k < 4; ++k) {
            unsigned xr = (unsigned)reflect1024(x0 + k);
            #pragma unroll
            for (int c = 0; c < 3; ++c) {
                ta[c][k] = x[baseA + (((unsigned)c) << 20) + xr];
                tb[c][k] = x[baseB + (((unsigned)c) << 20) + xr];
            }
        }
        a0 = make_float4(ta[0][0], ta[0][1], ta[0][2], ta[0][3]);
        a1 = make_float4(ta[1][0], ta[1][1], ta[1][2], ta[1][3]);
        a2 = make_float4(ta[2][0], ta[2][1], ta[2][2], ta[2][3]);
        c0 = make_float4(tb[0][0], tb[0][1], tb[0][2], tb[0][3]);
        c1 = make_float4(tb[1][0], tb[1][1], tb[1][2], tb[1][3]);
        c2 = make_float4(tb[2][0], tb[2][1], tb[2][2], tb[2][3]);
    }

    // ---- permute channel-major -> (pixel, channel); stage both rows ----
    smq[0][t * 3u + 0u] = make_float4(a0.x, a1.x, a2.x, a0.y);
    smq[0][t * 3u + 1u] = make_float4(a1.y, a2.y, a0.z, a1.z);
    smq[0][t * 3u + 2u] = make_float4(a2.z, a0.w, a1.w, a2.w);
    smq[1][t * 3u + 0u] = make_float4(c0.x, c1.x, c2.x, c0.y);
    smq[1][t * 3u + 1u] = make_float4(c1.y, c2.y, c0.z, c1.z);
    smq[1][t * 3u + 2u] = make_float4(c2.z, c0.w, c1.w, c2.w);
    __syncthreads();

    // ---- emit via async-proxy bulk stores: 128 x 288B, zero STG/LDS ----
    // thread t < 128: img = t>>6, patch-segment pwS = t&63
    if (t < 128u) {
        unsigned img = t >> 6;
        unsigned pwS = t & 63u;

        // order generic STS (by all threads, pre-barrier) before async-proxy read
        asm volatile("fence.proxy.async.shared::cta;" ::: "memory");

        unsigned outBase = ((b4 << 12) + (ph << 6)) * 432u + iu * 18u;
        size_t gdstF4 = (size_t)outBase + (size_t)img * B_OFF_OUT + (size_t)pwS * 432u;
        const char* gdst = reinterpret_cast<const char*>(
            reinterpret_cast<float4*>(out) + gdstF4);
        unsigned ssrc = (unsigned)__cvta_generic_to_shared(&smq[img][pwS * 18u]);

        asm volatile(
            "cp.async.bulk.global.shared::cta.bulk_group [%0], [%1], 288;"
            :: "l"(gdst), "r"(ssrc) : "memory");
        asm volatile("cp.async.bulk.commit_group;" ::: "memory");
        asm volatile("cp.async.bulk.wait_group 0;" ::: "memory");
    }
}

extern "C" void kernel_launch(void* const* d_in, const int* in_sizes, int n_in,
                              void* d_out, int out_size) {
    const float* x = (const float*)d_in[0];
    float* out = (float*)d_out;
    unsigned out_elems = (unsigned)out_size;

    unsigned extraElems  = (out_elems > PATCH_ELEMS) ? (out_elems - PATCH_ELEMS) : 0u;
    unsigned extraBlocks = (extraElems + THREADS - 1u) / THREADS;
    Patcher_78280073937146_kernel<<<NROWCTAS + extraBlocks, THREADS>>>(x, out, out_elems);
}